// round 2
// baseline (speedup 1.0000x reference)
#include <cuda_runtime.h>

// Fixed problem shape: N nodes == N edges, C = 64 channels.
#define NMAX 1048576
#define SCAN_CHUNK 4096               // elements per scan block
#define SCAN_NB (NMAX / SCAN_CHUNK)   // 256 scan blocks

// ---- persistent device scratch (no runtime allocation allowed) ----
__device__ float g_s[NMAX];          // s[i] = x[i] . w
__device__ float g_learned[NMAX];    // learned edge score per node
__device__ int   g_deg[NMAX];        // in-degree histogram
__device__ int   g_rowptr[NMAX + 1]; // CSR row pointers (by dst)
__device__ int   g_cursor[NMAX];     // scatter cursors (copy of rowptr)
__device__ int2  g_edge[NMAX];       // (src, bitcast(score)) sorted by dst
__device__ int   g_bsum[SCAN_NB];
__device__ int   g_boff[SCAN_NB];
__device__ int   g_is64;             // 1 if edge_index is int64, 0 if int32

// Edge accessor: which==0 -> src row, which==1 -> dst row.
__device__ __forceinline__ int eidx(const void* __restrict__ ei, int n,
                                    int which, int e, int is64) {
    if (is64) return (int)((const long long*)ei)[(size_t)which * n + e];
    return ((const int*)ei)[(size_t)which * n + e];
}

// K0: detect edge_index dtype on-device (graph-capturable).
// Genuine int64 indices < 2^31 always have a zero high word; int32 data
// reinterpreted as int64 has a random nonzero "high word" almost surely.
__global__ void k_detect(const void* __restrict__ ei) {
    if (threadIdx.x == 0 && blockIdx.x == 0) {
        const unsigned long long* p = (const unsigned long long*)ei;
        int is64 = 1;
        for (int k = 0; k < 256; k++) {
            if (p[k] >> 32) { is64 = 0; break; }
        }
        g_is64 = is64;
    }
}

// K1: warp-per-node dot product s[i] = x[i].w ; init learned = b, deg = 0.
__global__ void k_dot_init(const float* __restrict__ x,
                           const float* __restrict__ w,
                           const float* __restrict__ b,
                           int n) {
    int i    = blockIdx.x * (blockDim.x >> 5) + (threadIdx.x >> 5);
    int lane = threadIdx.x & 31;
    if (i >= n) return;
    float2 xv = reinterpret_cast<const float2*>(x + (size_t)i * 64)[lane];
    float2 wv = reinterpret_cast<const float2*>(w)[lane];
    float p = xv.x * wv.x + xv.y * wv.y;
    #pragma unroll
    for (int off = 16; off; off >>= 1) p += __shfl_down_sync(0xffffffffu, p, off);
    if (lane == 0) {
        g_s[i] = p;
        g_learned[i] = b[0];   // self-loop contributes lin(0) = b
        g_deg[i] = 0;
    }
}

// K2: per-edge — in-degree histogram + learned scatter (only dst >= first matters).
__global__ void k_edge_scatter1(const void* __restrict__ ei,
                                const float* __restrict__ b,
                                int n, int first) {
    int e = blockIdx.x * blockDim.x + threadIdx.x;
    if (e >= n) return;
    int is64 = g_is64;
    int src = eidx(ei, n, 0, e, is64);
    int dst = eidx(ei, n, 1, e, is64);
    atomicAdd(&g_deg[dst], 1);
    if (dst >= first) {
        atomicAdd(&g_learned[dst], g_s[src] - g_s[dst] + b[0]);
    }
}

// K3a: per-block partial sums of deg.
__global__ void k_scan_reduce() {
    __shared__ int sh[256];
    int base = blockIdx.x * SCAN_CHUNK;
    int t = threadIdx.x;
    int s = 0;
    #pragma unroll
    for (int k = 0; k < 16; k++) s += g_deg[base + t + k * 256];
    sh[t] = s;
    __syncthreads();
    for (int off = 128; off; off >>= 1) {
        if (t < off) sh[t] += sh[t + off];
        __syncthreads();
    }
    if (t == 0) g_bsum[blockIdx.x] = sh[0];
}

// K3b: tiny sequential exclusive scan of the 256 block sums.
__global__ void k_scan_offsets(int n) {
    if (threadIdx.x == 0 && blockIdx.x == 0) {
        int run = 0;
        for (int j = 0; j < SCAN_NB; j++) { g_boff[j] = run; run += g_bsum[j]; }
        g_rowptr[n] = run;   // == n (total edges)
    }
}

// K3c: in-block exclusive scan -> rowptr + cursor.
__global__ void k_scan_write() {
    __shared__ int sh[256];
    int t = threadIdx.x;
    int base = blockIdx.x * SCAN_CHUNK + t * 16;
    int loc[16];
    int tot = 0;
    #pragma unroll
    for (int k = 0; k < 16; k++) { loc[k] = g_deg[base + k]; tot += loc[k]; }
    sh[t] = tot;
    __syncthreads();
    if (t == 0) {
        int run = g_boff[blockIdx.x];
        for (int j = 0; j < 256; j++) { int tmp = sh[j]; sh[j] = run; run += tmp; }
    }
    __syncthreads();
    int run = sh[t];
    #pragma unroll
    for (int k = 0; k < 16; k++) {
        g_rowptr[base + k] = run;
        g_cursor[base + k] = run;
        run += loc[k];
    }
}

// K4: per-edge score + scatter (src, score) into dst-sorted slots.
// Edge k's score is indexed by the EDGE position k (reference uses scores[:e]).
__global__ void k_score_scatter(const void* __restrict__ ei,
                                const float* __restrict__ w1,
                                const float* __restrict__ w2,
                                const float* __restrict__ w3,
                                int n, int first) {
    int e = blockIdx.x * blockDim.x + threadIdx.x;
    if (e >= n) return;
    float sc;
    if (e < first) {
        sc = w1[0];
    } else {
        sc = (((e - first) & 1) ? w3[0] : w2[0]) + g_learned[e];
    }
    int is64 = g_is64;
    int dst = eidx(ei, n, 1, e, is64);
    int src = eidx(ei, n, 0, e, is64);
    int pos = atomicAdd(&g_cursor[dst], 1);
    g_edge[pos] = make_int2(src, __float_as_int(sc));
}

// K5: warp-per-node gather: out[i] = relu( sum_e x[src_e] * score_e ).
__global__ void k_gather(const float* __restrict__ x,
                         float* __restrict__ out, int n) {
    int i    = blockIdx.x * (blockDim.x >> 5) + (threadIdx.x >> 5);
    int lane = threadIdx.x & 31;
    if (i >= n) return;
    int r = (lane < 2) ? g_rowptr[i + lane] : 0;
    int r0 = __shfl_sync(0xffffffffu, r, 0);
    int r1 = __shfl_sync(0xffffffffu, r, 1);
    float2 acc = make_float2(0.f, 0.f);
    for (int p = r0; p < r1; p++) {
        int2 ev = g_edge[p];
        float v = __int_as_float(ev.y);
        float2 xv = reinterpret_cast<const float2*>(x + (size_t)ev.x * 64)[lane];
        acc.x = fmaf(xv.x, v, acc.x);
        acc.y = fmaf(xv.y, v, acc.y);
    }
    acc.x = fmaxf(acc.x, 0.f);
    acc.y = fmaxf(acc.y, 0.f);
    reinterpret_cast<float2*>(out + (size_t)i * 64)[lane] = acc;
}

extern "C" void kernel_launch(void* const* d_in, const int* in_sizes, int n_in,
                              void* d_out, int out_size) {
    const float* x     = (const float*)d_in[0];
    const float* lin_w = (const float*)d_in[1];
    const float* lin_b = (const float*)d_in[2];
    const float* w1    = (const float*)d_in[3];
    const float* w2    = (const float*)d_in[4];
    const float* w3    = (const float*)d_in[5];
    const void*  ei    = d_in[6];
    float* out = (float*)d_out;

    int n = in_sizes[6] / 2;     // edge_index is (2, N)
    int first = n / 3;

    int warpBlocks = (n + 7) / 8;           // 8 warps (256 threads) per block
    int edgeBlocks = (n + 255) / 256;

    k_detect       <<<1, 32>>>(ei);
    k_dot_init     <<<warpBlocks, 256>>>(x, lin_w, lin_b, n);
    k_edge_scatter1<<<edgeBlocks, 256>>>(ei, lin_b, n, first);
    k_scan_reduce  <<<SCAN_NB, 256>>>();
    k_scan_offsets <<<1, 32>>>(n);
    k_scan_write   <<<SCAN_NB, 256>>>();
    k_score_scatter<<<edgeBlocks, 256>>>(ei, w1, w2, w3, n, first);
    k_gather       <<<warpBlocks, 256>>>(x, out, n);
}

// round 3
// speedup vs baseline: 1.5739x; 1.5739x over previous
#include <cuda_runtime.h>

// Fixed problem shape: N nodes == N edges, C = 64 channels.
#define NMAX 1048576
#define SCAN_CHUNK 4096               // elements per scan block
#define SCAN_NB (NMAX / SCAN_CHUNK)   // 256 scan blocks

// ---- persistent device scratch (no runtime allocation allowed) ----
__device__ float g_s[NMAX];          // s[i] = x[i] . w
__device__ float g_learned[NMAX];    // learned edge score per node
__device__ int   g_deg[NMAX];        // in-degree histogram
__device__ int   g_rowptr[NMAX + 1]; // CSR row pointers (by dst)
__device__ int   g_cursor[NMAX];     // scatter cursors (copy of rowptr)
__device__ int2  g_sd[NMAX];         // (src, dst) decoded edge list (L2-resident)
__device__ int2  g_edge[NMAX];       // (src, bitcast(score)) sorted by dst
__device__ int   g_bsum[SCAN_NB];
__device__ int   g_boff[SCAN_NB];
__device__ int   g_is64;             // 1 if edge_index is int64, 0 if int32

// K0: detect edge_index dtype (parallel — one load per thread).
// Genuine int64 indices < 2^31 always have zero high words; int32 data
// reinterpreted as int64 has random nonzero "high words" almost surely.
__global__ void k_detect(const void* __restrict__ ei) {
    const unsigned long long* p = (const unsigned long long*)ei;
    int bad = (p[threadIdx.x] >> 32) != 0ull;
    bad = __syncthreads_or(bad);
    if (threadIdx.x == 0) g_is64 = !bad;
}

// K1: 2 nodes per warp (16 lanes each, float4): s[i] = x[i].w ; init learned/deg.
__global__ void k_dot_init(const float* __restrict__ x,
                           const float* __restrict__ w,
                           const float* __restrict__ b,
                           int n) {
    int wrp  = blockIdx.x * (blockDim.x >> 5) + (threadIdx.x >> 5);
    int lane = threadIdx.x & 31;
    int half = lane >> 4;
    int l    = lane & 15;
    int i = wrp * 2 + half;
    if (i >= n) return;
    float4 xv = reinterpret_cast<const float4*>(x + (size_t)i * 64)[l];
    float4 wv = reinterpret_cast<const float4*>(w)[l];
    float p = xv.x * wv.x + xv.y * wv.y + xv.z * wv.z + xv.w * wv.w;
    #pragma unroll
    for (int off = 8; off; off >>= 1) p += __shfl_down_sync(0xffffffffu, p, off, 16);
    if (l == 0) {
        g_s[i] = p;
        g_learned[i] = b[0];   // self-loop contributes lin(0) = b
        g_deg[i] = 0;
    }
}

// K2: per-edge — decode indices once, in-degree histogram + learned scatter.
__global__ void k_edge_scatter1(const void* __restrict__ ei,
                                const float* __restrict__ b,
                                int n, int first) {
    int e = blockIdx.x * blockDim.x + threadIdx.x;
    if (e >= n) return;
    int src, dst;
    if (g_is64) {
        src = (int)((const long long*)ei)[e];
        dst = (int)((const long long*)ei)[(size_t)n + e];
    } else {
        src = ((const int*)ei)[e];
        dst = ((const int*)ei)[(size_t)n + e];
    }
    g_sd[e] = make_int2(src, dst);
    atomicAdd(&g_deg[dst], 1);
    if (dst >= first) {
        atomicAdd(&g_learned[dst], g_s[src] - g_s[dst] + b[0]);
    }
}

// K3a: per-block partial sums of deg.
__global__ void k_scan_reduce() {
    __shared__ int sh[256];
    int base = blockIdx.x * SCAN_CHUNK;
    int t = threadIdx.x;
    int s = 0;
    #pragma unroll
    for (int k = 0; k < 16; k++) s += g_deg[base + t + k * 256];
    sh[t] = s;
    __syncthreads();
    for (int off = 128; off; off >>= 1) {
        if (t < off) sh[t] += sh[t + off];
        __syncthreads();
    }
    if (t == 0) g_bsum[blockIdx.x] = sh[0];
}

// K3b: tiny sequential exclusive scan of the 256 block sums.
__global__ void k_scan_offsets(int n) {
    if (threadIdx.x == 0 && blockIdx.x == 0) {
        int run = 0;
        for (int j = 0; j < SCAN_NB; j++) { g_boff[j] = run; run += g_bsum[j]; }
        g_rowptr[n] = run;   // == n (total edges)
    }
}

// K3c: in-block exclusive scan -> rowptr + cursor.
__global__ void k_scan_write() {
    __shared__ int sh[256];
    int t = threadIdx.x;
    int base = blockIdx.x * SCAN_CHUNK + t * 16;
    int loc[16];
    int tot = 0;
    #pragma unroll
    for (int k = 0; k < 16; k++) { loc[k] = g_deg[base + k]; tot += loc[k]; }
    sh[t] = tot;
    __syncthreads();
    if (t == 0) {
        int run = g_boff[blockIdx.x];
        for (int j = 0; j < 256; j++) { int tmp = sh[j]; sh[j] = run; run += tmp; }
    }
    __syncthreads();
    int run = sh[t];
    #pragma unroll
    for (int k = 0; k < 16; k++) {
        g_rowptr[base + k] = run;
        g_cursor[base + k] = run;
        run += loc[k];
    }
}

// K4: per-edge score + scatter (src, score) into dst-sorted slots.
// Edge k's score is indexed by the EDGE position k (reference uses scores[:e]).
__global__ void k_score_scatter(const float* __restrict__ w1,
                                const float* __restrict__ w2,
                                const float* __restrict__ w3,
                                int n, int first) {
    int e = blockIdx.x * blockDim.x + threadIdx.x;
    if (e >= n) return;
    float sc;
    if (e < first) {
        sc = w1[0];
    } else {
        sc = (((e - first) & 1) ? w3[0] : w2[0]) + g_learned[e];
    }
    int2 sd = g_sd[e];
    int pos = atomicAdd(&g_cursor[sd.y], 1);
    g_edge[pos] = make_int2(sd.x, __float_as_int(sc));
}

// K5: 2 nodes per warp gather: out[i] = relu( sum_e x[src_e] * score_e ).
// 16 lanes per node, float4 per lane covers the 64-float row; the two halves
// run independent edge loops -> 2x memory-level parallelism per warp.
__global__ void k_gather(const float* __restrict__ x,
                         float* __restrict__ out, int n) {
    int wrp  = blockIdx.x * (blockDim.x >> 5) + (threadIdx.x >> 5);
    int lane = threadIdx.x & 31;
    int half = lane >> 4;
    int l    = lane & 15;
    int i = wrp * 2 + half;
    if (i >= n) return;
    int r0 = g_rowptr[i];
    int r1 = g_rowptr[i + 1];
    float4 acc = make_float4(0.f, 0.f, 0.f, 0.f);
    for (int p = r0; p < r1; p++) {
        int2 ev = g_edge[p];                       // broadcast within half-warp
        float v = __int_as_float(ev.y);
        float4 xv = reinterpret_cast<const float4*>(x + (size_t)ev.x * 64)[l];
        acc.x = fmaf(xv.x, v, acc.x);
        acc.y = fmaf(xv.y, v, acc.y);
        acc.z = fmaf(xv.z, v, acc.z);
        acc.w = fmaf(xv.w, v, acc.w);
    }
    acc.x = fmaxf(acc.x, 0.f);
    acc.y = fmaxf(acc.y, 0.f);
    acc.z = fmaxf(acc.z, 0.f);
    acc.w = fmaxf(acc.w, 0.f);
    reinterpret_cast<float4*>(out + (size_t)i * 64)[l] = acc;
}

extern "C" void kernel_launch(void* const* d_in, const int* in_sizes, int n_in,
                              void* d_out, int out_size) {
    const float* x     = (const float*)d_in[0];
    const float* lin_w = (const float*)d_in[1];
    const float* lin_b = (const float*)d_in[2];
    const float* w1    = (const float*)d_in[3];
    const float* w2    = (const float*)d_in[4];
    const float* w3    = (const float*)d_in[5];
    const void*  ei    = d_in[6];
    float* out = (float*)d_out;

    int n = in_sizes[6] / 2;     // edge_index is (2, N)
    int first = n / 3;

    int nodeBlocks = (n + 15) / 16;         // 8 warps/block, 2 nodes/warp
    int edgeBlocks = (n + 255) / 256;

    k_detect       <<<1, 256>>>(ei);
    k_dot_init     <<<nodeBlocks, 256>>>(x, lin_w, lin_b, n);
    k_edge_scatter1<<<edgeBlocks, 256>>>(ei, lin_b, n, first);
    k_scan_reduce  <<<SCAN_NB, 256>>>();
    k_scan_offsets <<<1, 32>>>(n);
    k_scan_write   <<<SCAN_NB, 256>>>();
    k_score_scatter<<<edgeBlocks, 256>>>(w1, w2, w3, n, first);
    k_gather       <<<nodeBlocks, 256>>>(x, out, n);
}

// round 4
// speedup vs baseline: 1.8359x; 1.1664x over previous
#include <cuda_runtime.h>

// Fixed problem shape: N nodes == N edges, C = 64 channels.
#define NMAX 1048576
#define SCAN_CHUNK 4096               // elements per scan block
#define SCAN_NB (NMAX / SCAN_CHUNK)   // 256 scan blocks

// ---- persistent device scratch (no runtime allocation allowed) ----
__device__ float g_s[NMAX];          // s[i] = x[i] . w
__device__ float g_learned[NMAX];    // learned edge score per node
__device__ int   g_deg[NMAX];        // in-degree histogram
__device__ int   g_rowptr[NMAX + 1]; // CSR row pointers (by dst)
__device__ int   g_cursor[NMAX];     // scatter cursors (copy of rowptr)
__device__ int2  g_sd[NMAX];         // (src, dst) decoded edge list
__device__ int2  g_edge[NMAX];       // (src, bitcast(score)) sorted by dst
__device__ unsigned long long g_state[SCAN_NB];  // lookback state (val<<2 | flag)
__device__ int   g_is64;             // 1 if edge_index is int64, 0 if int32

// K1: 2 nodes per warp (16 lanes, float4): s[i] = x[i].w ; init learned/deg.
// Block 0 additionally resets the scan lookback state and detects the
// edge_index dtype (consumed only by the NEXT launch -> ordering safe).
__global__ void k_dot_init(const float* __restrict__ x,
                           const float* __restrict__ w,
                           const float* __restrict__ b,
                           const void* __restrict__ ei,
                           int n) {
    if (blockIdx.x == 0) {
        __shared__ int s_bad;
        if (threadIdx.x == 0) s_bad = 0;
        g_state[threadIdx.x] = 0ull;
        __syncthreads();
        // Genuine int64 indices < 2^31 have zero high words; int32 data
        // reinterpreted as int64 has random nonzero high words almost surely.
        if (((const unsigned long long*)ei)[threadIdx.x] >> 32) s_bad = 1;
        __syncthreads();
        if (threadIdx.x == 0) g_is64 = !s_bad;
    }
    int wrp  = blockIdx.x * (blockDim.x >> 5) + (threadIdx.x >> 5);
    int lane = threadIdx.x & 31;
    int half = lane >> 4;
    int l    = lane & 15;
    int i = wrp * 2 + half;
    if (i >= n) return;
    float4 xv = reinterpret_cast<const float4*>(x + (size_t)i * 64)[l];
    float4 wv = reinterpret_cast<const float4*>(w)[l];
    float p = xv.x * wv.x + xv.y * wv.y + xv.z * wv.z + xv.w * wv.w;
    #pragma unroll
    for (int off = 8; off; off >>= 1) p += __shfl_down_sync(0xffffffffu, p, off, 16);
    if (l == 0) {
        g_s[i] = p;
        g_learned[i] = b[0];   // self-loop contributes lin(0) = b
        g_deg[i] = 0;
    }
}

// K2: per-edge — decode indices once, in-degree histogram + learned scatter.
__global__ void k_edge_scatter1(const void* __restrict__ ei,
                                const float* __restrict__ b,
                                int n, int first) {
    int e = blockIdx.x * blockDim.x + threadIdx.x;
    if (e >= n) return;
    int src, dst;
    if (g_is64) {
        src = (int)((const long long*)ei)[e];
        dst = (int)((const long long*)ei)[(size_t)n + e];
    } else {
        src = ((const int*)ei)[e];
        dst = ((const int*)ei)[(size_t)n + e];
    }
    g_sd[e] = make_int2(src, dst);
    atomicAdd(&g_deg[dst], 1);
    if (dst >= first) {
        atomicAdd(&g_learned[dst], g_s[src] - g_s[dst] + b[0]);
    }
}

// K3: single-pass exclusive scan of g_deg -> rowptr + cursor
// (decoupled lookback; all 256 blocks are co-resident on 148 SMs).
__global__ void k_scan(int n) {
    __shared__ int sh[256];
    __shared__ int s_off;
    int b = blockIdx.x, t = threadIdx.x;
    int base = b * SCAN_CHUNK + t * 16;
    int loc[16];
    int tot = 0;
    #pragma unroll
    for (int k = 0; k < 16; k++) { loc[k] = g_deg[base + k]; tot += loc[k]; }
    sh[t] = tot;
    __syncthreads();
    // Hillis-Steele inclusive scan over the 256 per-thread sums.
    for (int off = 1; off < 256; off <<= 1) {
        int add = (t >= off) ? sh[t - off] : 0;
        __syncthreads();
        sh[t] += add;
        __syncthreads();
    }
    if (t == 0) {
        int total = sh[255];
        atomicExch(&g_state[b], ((unsigned long long)total << 2) | 1ull);  // AGG
        long long sum = 0;
        for (int j = b - 1; j >= 0; ) {
            unsigned long long st;
            do { st = atomicAdd(&g_state[j], 0ull); } while ((st & 3ull) == 0ull);
            sum += (long long)(st >> 2);
            if ((st & 3ull) == 2ull) break;   // PREFIX -> done
            j--;
        }
        atomicExch(&g_state[b],
                   (((unsigned long long)(sum + total)) << 2) | 2ull);     // PREFIX
        s_off = (int)sum;
        if (b == SCAN_NB - 1) g_rowptr[n] = (int)(sum + total);
    }
    __syncthreads();
    int run = s_off + sh[t] - tot;   // exclusive prefix for this thread's chunk
    #pragma unroll
    for (int k = 0; k < 16; k++) {
        g_rowptr[base + k] = run;
        g_cursor[base + k] = run;
        run += loc[k];
    }
}

// K4: per-edge score + scatter (src, score) into dst-sorted slots.
// Edge k's score is indexed by the EDGE position k (reference uses scores[:e]).
__global__ void k_score_scatter(const float* __restrict__ w1,
                                const float* __restrict__ w2,
                                const float* __restrict__ w3,
                                int n, int first) {
    int e = blockIdx.x * blockDim.x + threadIdx.x;
    if (e >= n) return;
    float sc;
    if (e < first) {
        sc = w1[0];
    } else {
        sc = (((e - first) & 1) ? w3[0] : w2[0]) + g_learned[e];
    }
    int2 sd = g_sd[e];
    int pos = atomicAdd(&g_cursor[sd.y], 1);
    g_edge[pos] = make_int2(sd.x, __float_as_int(sc));
}

// K5: 4 nodes per warp gather: out[i] = relu( sum_e x[src_e] * score_e ).
// 8 lanes per node, 2x float4 per lane covers the 64-float row; four
// independent edge loops per warp -> 4x memory-level parallelism.
__global__ void k_gather(const float* __restrict__ x,
                         float* __restrict__ out, int n) {
    int wrp  = blockIdx.x * (blockDim.x >> 5) + (threadIdx.x >> 5);
    int lane = threadIdx.x & 31;
    int q = lane >> 3;
    int l = lane & 7;
    int i = wrp * 4 + q;
    if (i >= n) return;
    int r0 = g_rowptr[i];
    int r1 = g_rowptr[i + 1];
    float4 a0 = make_float4(0.f, 0.f, 0.f, 0.f);
    float4 a1 = make_float4(0.f, 0.f, 0.f, 0.f);
    for (int p = r0; p < r1; p++) {
        int2 ev = g_edge[p];                   // broadcast within 8-lane group
        float v = __int_as_float(ev.y);
        const float4* row = reinterpret_cast<const float4*>(x + (size_t)ev.x * 64);
        float4 x0 = row[l];
        float4 x1 = row[l + 8];
        a0.x = fmaf(x0.x, v, a0.x); a0.y = fmaf(x0.y, v, a0.y);
        a0.z = fmaf(x0.z, v, a0.z); a0.w = fmaf(x0.w, v, a0.w);
        a1.x = fmaf(x1.x, v, a1.x); a1.y = fmaf(x1.y, v, a1.y);
        a1.z = fmaf(x1.z, v, a1.z); a1.w = fmaf(x1.w, v, a1.w);
    }
    a0.x = fmaxf(a0.x, 0.f); a0.y = fmaxf(a0.y, 0.f);
    a0.z = fmaxf(a0.z, 0.f); a0.w = fmaxf(a0.w, 0.f);
    a1.x = fmaxf(a1.x, 0.f); a1.y = fmaxf(a1.y, 0.f);
    a1.z = fmaxf(a1.z, 0.f); a1.w = fmaxf(a1.w, 0.f);
    float4* orow = reinterpret_cast<float4*>(out + (size_t)i * 64);
    orow[l]     = a0;
    orow[l + 8] = a1;
}

extern "C" void kernel_launch(void* const* d_in, const int* in_sizes, int n_in,
                              void* d_out, int out_size) {
    const float* x     = (const float*)d_in[0];
    const float* lin_w = (const float*)d_in[1];
    const float* lin_b = (const float*)d_in[2];
    const float* w1    = (const float*)d_in[3];
    const float* w2    = (const float*)d_in[4];
    const float* w3    = (const float*)d_in[5];
    const void*  ei    = d_in[6];
    float* out = (float*)d_out;

    int n = in_sizes[6] / 2;     // edge_index is (2, N)
    int first = n / 3;

    int dotBlocks    = (n + 15) / 16;       // 8 warps/block, 2 nodes/warp
    int gatherBlocks = (n + 31) / 32;       // 8 warps/block, 4 nodes/warp
    int edgeBlocks   = (n + 255) / 256;

    k_dot_init     <<<dotBlocks, 256>>>(x, lin_w, lin_b, ei, n);
    k_edge_scatter1<<<edgeBlocks, 256>>>(ei, lin_b, n, first);
    k_scan         <<<SCAN_NB, 256>>>(n);
    k_score_scatter<<<edgeBlocks, 256>>>(w1, w2, w3, n, first);
    k_gather       <<<gatherBlocks, 256>>>(x, out, n);
}

// round 5
// speedup vs baseline: 1.9516x; 1.0630x over previous
#include <cuda_runtime.h>

// Fixed problem shape: N nodes == N edges, C = 64 channels.
#define NMAX 1048576
#define SCAN_CHUNK 4096               // elements per scan block
#define SCAN_NB (NMAX / SCAN_CHUNK)   // 256 scan blocks

// ---- persistent device scratch (no runtime allocation allowed) ----
__device__ float g_s[NMAX];          // s[i] = x[i] . w
__device__ float g_learned[NMAX];    // learned edge score per node
__device__ int   g_deg[NMAX];        // in-degree histogram
__device__ int   g_rowptr[NMAX + 1]; // CSR row pointers (by dst)
__device__ int   g_cursor[NMAX];     // scatter cursors (copy of rowptr)
__device__ int2  g_sd[NMAX];         // (src, dst) decoded edge list
__device__ int2  g_edge[NMAX];       // (src, bitcast(score)) sorted by dst
__device__ unsigned long long g_state[SCAN_NB];  // lookback state (val<<2 | flag)
__device__ int   g_is64;             // 1 if edge_index is int64, 0 if int32

// K1: 2 nodes per warp (16 lanes, float4): s[i] = x[i].w ; init learned/deg.
// Block 0 additionally resets the scan lookback state and detects the
// edge_index dtype (consumed only by the NEXT launch -> ordering safe).
__global__ void k_dot_init(const float* __restrict__ x,
                           const float* __restrict__ w,
                           const float* __restrict__ b,
                           const void* __restrict__ ei,
                           int n) {
    if (blockIdx.x == 0) {
        __shared__ int s_bad;
        if (threadIdx.x == 0) s_bad = 0;
        g_state[threadIdx.x] = 0ull;
        __syncthreads();
        // Genuine int64 indices < 2^31 have zero high words; int32 data
        // reinterpreted as int64 has random nonzero high words almost surely.
        if (((const unsigned long long*)ei)[threadIdx.x] >> 32) s_bad = 1;
        __syncthreads();
        if (threadIdx.x == 0) g_is64 = !s_bad;
    }
    int wrp  = blockIdx.x * (blockDim.x >> 5) + (threadIdx.x >> 5);
    int lane = threadIdx.x & 31;
    int half = lane >> 4;
    int l    = lane & 15;
    int i = wrp * 2 + half;
    if (i >= n) return;
    float4 xv = reinterpret_cast<const float4*>(x + (size_t)i * 64)[l];
    float4 wv = reinterpret_cast<const float4*>(w)[l];
    float p = xv.x * wv.x + xv.y * wv.y + xv.z * wv.z + xv.w * wv.w;
    #pragma unroll
    for (int off = 8; off; off >>= 1) p += __shfl_down_sync(0xffffffffu, p, off, 16);
    if (l == 0) {
        g_s[i] = p;
        g_learned[i] = b[0];   // self-loop contributes lin(0) = b
        g_deg[i] = 0;
    }
}

// K2: per-edge — decode indices once, in-degree histogram + learned scatter.
__global__ void k_edge_scatter1(const void* __restrict__ ei,
                                const float* __restrict__ b,
                                int n, int first) {
    int e = blockIdx.x * blockDim.x + threadIdx.x;
    if (e >= n) return;
    int src, dst;
    if (g_is64) {
        src = (int)((const long long*)ei)[e];
        dst = (int)((const long long*)ei)[(size_t)n + e];
    } else {
        src = ((const int*)ei)[e];
        dst = ((const int*)ei)[(size_t)n + e];
    }
    g_sd[e] = make_int2(src, dst);
    atomicAdd(&g_deg[dst], 1);
    if (dst >= first) {
        atomicAdd(&g_learned[dst], g_s[src] - g_s[dst] + b[0]);
    }
}

// K3: single-pass exclusive scan of g_deg -> rowptr + cursor
// (decoupled lookback; all 256 blocks are co-resident on 148 SMs).
__global__ void k_scan(int n) {
    __shared__ int sh[256];
    __shared__ int s_off;
    int b = blockIdx.x, t = threadIdx.x;
    int base = b * SCAN_CHUNK + t * 16;
    int4 v0 = reinterpret_cast<const int4*>(g_deg + base)[0];
    int4 v1 = reinterpret_cast<const int4*>(g_deg + base)[1];
    int4 v2 = reinterpret_cast<const int4*>(g_deg + base)[2];
    int4 v3 = reinterpret_cast<const int4*>(g_deg + base)[3];
    int loc[16] = {v0.x, v0.y, v0.z, v0.w, v1.x, v1.y, v1.z, v1.w,
                   v2.x, v2.y, v2.z, v2.w, v3.x, v3.y, v3.z, v3.w};
    int tot = 0;
    #pragma unroll
    for (int k = 0; k < 16; k++) tot += loc[k];
    sh[t] = tot;
    __syncthreads();
    // Hillis-Steele inclusive scan over the 256 per-thread sums.
    for (int off = 1; off < 256; off <<= 1) {
        int add = (t >= off) ? sh[t - off] : 0;
        __syncthreads();
        sh[t] += add;
        __syncthreads();
    }
    if (t == 0) {
        int total = sh[255];
        atomicExch(&g_state[b], ((unsigned long long)total << 2) | 1ull);  // AGG
        long long sum = 0;
        for (int j = b - 1; j >= 0; ) {
            unsigned long long st;
            do { st = atomicAdd(&g_state[j], 0ull); } while ((st & 3ull) == 0ull);
            sum += (long long)(st >> 2);
            if ((st & 3ull) == 2ull) break;   // PREFIX -> done
            j--;
        }
        atomicExch(&g_state[b],
                   (((unsigned long long)(sum + total)) << 2) | 2ull);     // PREFIX
        s_off = (int)sum;
        if (b == SCAN_NB - 1) g_rowptr[n] = (int)(sum + total);
    }
    __syncthreads();
    int run = s_off + sh[t] - tot;   // exclusive prefix for this thread's chunk
    #pragma unroll
    for (int k = 0; k < 16; k++) {
        g_rowptr[base + k] = run;
        g_cursor[base + k] = run;
        run += loc[k];
    }
}

// K4: per-edge score + scatter (src, score) into dst-sorted slots.
// 2 edges per thread for 2 independent atomic->store chains.
// Edge k's score is indexed by the EDGE position k (reference uses scores[:e]).
__global__ void k_score_scatter(const float* __restrict__ w1,
                                const float* __restrict__ w2,
                                const float* __restrict__ w3,
                                int n, int first) {
    int e0 = (blockIdx.x * blockDim.x + threadIdx.x) * 2;
    float cw1 = w1[0], cw2 = w2[0], cw3 = w3[0];
    #pragma unroll
    for (int k = 0; k < 2; k++) {
        int e = e0 + k;
        if (e >= n) return;
        float sc;
        if (e < first) {
            sc = cw1;
        } else {
            sc = (((e - first) & 1) ? cw3 : cw2) + g_learned[e];
        }
        int2 sd = g_sd[e];
        int pos = atomicAdd(&g_cursor[sd.y], 1);
        g_edge[pos] = make_int2(sd.x, __float_as_int(sc));
    }
}

// K5: 8 nodes per warp gather: out[i] = relu( sum_e x[src_e] * score_e ).
// 4 lanes per node, 4x float4 per lane covers the 64-float row; eight
// independent edge loops per warp, 4 independent row loads per lane.
__global__ void k_gather(const float* __restrict__ x,
                         float* __restrict__ out, int n) {
    int wrp  = blockIdx.x * (blockDim.x >> 5) + (threadIdx.x >> 5);
    int lane = threadIdx.x & 31;
    int q = lane >> 2;      // node slot within warp (0..7)
    int l = lane & 3;       // lane within node
    int i = wrp * 8 + q;
    if (i >= n) return;
    int r0 = g_rowptr[i];
    int r1 = g_rowptr[i + 1];
    float4 a0 = make_float4(0.f, 0.f, 0.f, 0.f);
    float4 a1 = make_float4(0.f, 0.f, 0.f, 0.f);
    float4 a2 = make_float4(0.f, 0.f, 0.f, 0.f);
    float4 a3 = make_float4(0.f, 0.f, 0.f, 0.f);
    for (int p = r0; p < r1; p++) {
        int2 ev = g_edge[p];                   // broadcast within 4-lane group
        float v = __int_as_float(ev.y);
        const float4* row = reinterpret_cast<const float4*>(x + (size_t)ev.x * 64);
        float4 x0 = row[l];
        float4 x1 = row[l + 4];
        float4 x2 = row[l + 8];
        float4 x3 = row[l + 12];
        a0.x = fmaf(x0.x, v, a0.x); a0.y = fmaf(x0.y, v, a0.y);
        a0.z = fmaf(x0.z, v, a0.z); a0.w = fmaf(x0.w, v, a0.w);
        a1.x = fmaf(x1.x, v, a1.x); a1.y = fmaf(x1.y, v, a1.y);
        a1.z = fmaf(x1.z, v, a1.z); a1.w = fmaf(x1.w, v, a1.w);
        a2.x = fmaf(x2.x, v, a2.x); a2.y = fmaf(x2.y, v, a2.y);
        a2.z = fmaf(x2.z, v, a2.z); a2.w = fmaf(x2.w, v, a2.w);
        a3.x = fmaf(x3.x, v, a3.x); a3.y = fmaf(x3.y, v, a3.y);
        a3.z = fmaf(x3.z, v, a3.z); a3.w = fmaf(x3.w, v, a3.w);
    }
    a0.x = fmaxf(a0.x, 0.f); a0.y = fmaxf(a0.y, 0.f);
    a0.z = fmaxf(a0.z, 0.f); a0.w = fmaxf(a0.w, 0.f);
    a1.x = fmaxf(a1.x, 0.f); a1.y = fmaxf(a1.y, 0.f);
    a1.z = fmaxf(a1.z, 0.f); a1.w = fmaxf(a1.w, 0.f);
    a2.x = fmaxf(a2.x, 0.f); a2.y = fmaxf(a2.y, 0.f);
    a2.z = fmaxf(a2.z, 0.f); a2.w = fmaxf(a2.w, 0.f);
    a3.x = fmaxf(a3.x, 0.f); a3.y = fmaxf(a3.y, 0.f);
    a3.z = fmaxf(a3.z, 0.f); a3.w = fmaxf(a3.w, 0.f);
    float4* orow = reinterpret_cast<float4*>(out + (size_t)i * 64);
    orow[l]      = a0;
    orow[l + 4]  = a1;
    orow[l + 8]  = a2;
    orow[l + 12] = a3;
}

extern "C" void kernel_launch(void* const* d_in, const int* in_sizes, int n_in,
                              void* d_out, int out_size) {
    const float* x     = (const float*)d_in[0];
    const float* lin_w = (const float*)d_in[1];
    const float* lin_b = (const float*)d_in[2];
    const float* w1    = (const float*)d_in[3];
    const float* w2    = (const float*)d_in[4];
    const float* w3    = (const float*)d_in[5];
    const void*  ei    = d_in[6];
    float* out = (float*)d_out;

    int n = in_sizes[6] / 2;     // edge_index is (2, N)
    int first = n / 3;

    int dotBlocks    = (n + 15) / 16;       // 8 warps/block, 2 nodes/warp
    int gatherBlocks = (n + 63) / 64;       // 8 warps/block, 8 nodes/warp
    int edgeBlocks   = (n + 255) / 256;
    int scoreBlocks  = (n + 511) / 512;     // 2 edges/thread

    k_dot_init     <<<dotBlocks, 256>>>(x, lin_w, lin_b, ei, n);
    k_edge_scatter1<<<edgeBlocks, 256>>>(ei, lin_b, n, first);
    k_scan         <<<SCAN_NB, 256>>>(n);
    k_score_scatter<<<scoreBlocks, 256>>>(w1, w2, w3, n, first);
    k_gather       <<<gatherBlocks, 256>>>(x, out, n);
}

// round 6
// speedup vs baseline: 1.9617x; 1.0052x over previous
#include <cuda_runtime.h>

// Fixed problem shape: N nodes == N edges, C = 64 channels.
#define NMAX 1048576
#define SCAN_CHUNK 4096               // elements per scan block
#define SCAN_NB (NMAX / SCAN_CHUNK)   // 256 scan blocks

// ---- persistent device scratch (no runtime allocation allowed) ----
__device__ float g_s[NMAX];          // s[i] = x[i] . w
__device__ float g_learned[NMAX];    // learned edge score per node
__device__ int   g_deg[NMAX];        // in-degree histogram
__device__ int   g_rank[NMAX];       // per-edge rank within its dst row
__device__ int   g_rowptr[NMAX + 1]; // CSR row pointers (by dst)
__device__ int2  g_sd[NMAX];         // (src, dst) decoded edge list
__device__ int2  g_edge[NMAX];       // (src, bitcast(score)) sorted by dst
__device__ unsigned long long g_state[SCAN_NB];  // lookback state (val<<2 | flag)
__device__ int   g_is64;             // 1 if edge_index is int64, 0 if int32

// K1: 2 nodes per warp (16 lanes, float4): s[i] = x[i].w ; init learned/deg.
// Block 0 additionally resets the scan lookback state and detects the
// edge_index dtype (consumed only by the NEXT launch -> ordering safe).
__global__ void k_dot_init(const float* __restrict__ x,
                           const float* __restrict__ w,
                           const float* __restrict__ b,
                           const void* __restrict__ ei,
                           int n) {
    if (blockIdx.x == 0) {
        __shared__ int s_bad;
        if (threadIdx.x == 0) s_bad = 0;
        g_state[threadIdx.x] = 0ull;
        __syncthreads();
        // Genuine int64 indices < 2^31 have zero high words; int32 data
        // reinterpreted as int64 has random nonzero high words almost surely.
        if (((const unsigned long long*)ei)[threadIdx.x] >> 32) s_bad = 1;
        __syncthreads();
        if (threadIdx.x == 0) g_is64 = !s_bad;
    }
    int wrp  = blockIdx.x * (blockDim.x >> 5) + (threadIdx.x >> 5);
    int lane = threadIdx.x & 31;
    int half = lane >> 4;
    int l    = lane & 15;
    int i = wrp * 2 + half;
    if (i >= n) return;
    float4 xv = reinterpret_cast<const float4*>(x + (size_t)i * 64)[l];
    float4 wv = reinterpret_cast<const float4*>(w)[l];
    float p = xv.x * wv.x + xv.y * wv.y + xv.z * wv.z + xv.w * wv.w;
    #pragma unroll
    for (int off = 8; off; off >>= 1) p += __shfl_down_sync(0xffffffffu, p, off, 16);
    if (l == 0) {
        g_s[i] = p;
        g_learned[i] = b[0];   // self-loop contributes lin(0) = b
        g_deg[i] = 0;
    }
}

// K2: per-edge — decode indices once, degree histogram (returning each edge's
// rank within its dst row) + learned scatter.
__global__ void k_edge_scatter1(const void* __restrict__ ei,
                                const float* __restrict__ b,
                                int n, int first) {
    int e = blockIdx.x * blockDim.x + threadIdx.x;
    if (e >= n) return;
    int src, dst;
    if (g_is64) {
        src = (int)((const long long*)ei)[e];
        dst = (int)((const long long*)ei)[(size_t)n + e];
    } else {
        src = ((const int*)ei)[e];
        dst = ((const int*)ei)[(size_t)n + e];
    }
    g_sd[e] = make_int2(src, dst);
    g_rank[e] = atomicAdd(&g_deg[dst], 1);
    if (dst >= first) {
        atomicAdd(&g_learned[dst], g_s[src] - g_s[dst] + b[0]);
    }
}

// K3: single-pass exclusive scan of g_deg -> rowptr
// (decoupled lookback; all 256 blocks are co-resident on 148 SMs).
__global__ void k_scan(int n) {
    __shared__ int sh[256];
    __shared__ int s_off;
    int b = blockIdx.x, t = threadIdx.x;
    int base = b * SCAN_CHUNK + t * 16;
    int4 v0 = reinterpret_cast<const int4*>(g_deg + base)[0];
    int4 v1 = reinterpret_cast<const int4*>(g_deg + base)[1];
    int4 v2 = reinterpret_cast<const int4*>(g_deg + base)[2];
    int4 v3 = reinterpret_cast<const int4*>(g_deg + base)[3];
    int loc[16] = {v0.x, v0.y, v0.z, v0.w, v1.x, v1.y, v1.z, v1.w,
                   v2.x, v2.y, v2.z, v2.w, v3.x, v3.y, v3.z, v3.w};
    int tot = 0;
    #pragma unroll
    for (int k = 0; k < 16; k++) tot += loc[k];
    sh[t] = tot;
    __syncthreads();
    // Hillis-Steele inclusive scan over the 256 per-thread sums.
    for (int off = 1; off < 256; off <<= 1) {
        int add = (t >= off) ? sh[t - off] : 0;
        __syncthreads();
        sh[t] += add;
        __syncthreads();
    }
    if (t == 0) {
        int total = sh[255];
        atomicExch(&g_state[b], ((unsigned long long)total << 2) | 1ull);  // AGG
        long long sum = 0;
        for (int j = b - 1; j >= 0; ) {
            unsigned long long st;
            do { st = atomicAdd(&g_state[j], 0ull); } while ((st & 3ull) == 0ull);
            sum += (long long)(st >> 2);
            if ((st & 3ull) == 2ull) break;   // PREFIX -> done
            j--;
        }
        atomicExch(&g_state[b],
                   (((unsigned long long)(sum + total)) << 2) | 2ull);     // PREFIX
        s_off = (int)sum;
        if (b == SCAN_NB - 1) g_rowptr[n] = (int)(sum + total);
    }
    __syncthreads();
    int run = s_off + sh[t] - tot;   // exclusive prefix for this thread's chunk
    #pragma unroll
    for (int k = 0; k < 16; k++) {
        g_rowptr[base + k] = run;
        run += loc[k];
    }
}

// K4: per-edge score + ATOMIC-FREE scatter: pos = rowptr[dst] + rank[e].
// 2 edges per thread for 2 independent read->write chains.
// Edge k's score is indexed by the EDGE position k (reference uses scores[:e]).
__global__ void k_score_scatter(const float* __restrict__ w1,
                                const float* __restrict__ w2,
                                const float* __restrict__ w3,
                                int n, int first) {
    int e0 = (blockIdx.x * blockDim.x + threadIdx.x) * 2;
    float cw1 = w1[0], cw2 = w2[0], cw3 = w3[0];
    #pragma unroll
    for (int k = 0; k < 2; k++) {
        int e = e0 + k;
        if (e >= n) return;
        float sc;
        if (e < first) {
            sc = cw1;
        } else {
            sc = (((e - first) & 1) ? cw3 : cw2) + g_learned[e];
        }
        int2 sd = g_sd[e];
        int pos = g_rowptr[sd.y] + g_rank[e];
        g_edge[pos] = make_int2(sd.x, __float_as_int(sc));
    }
}

// K5: 8 nodes per warp gather: out[i] = relu( sum_e x[src_e] * score_e ).
// 4 lanes per node, 4x float4 per lane covers the 64-float row; eight
// independent edge loops per warp. Edge loop manually unrolled by 2 so
// that 8 independent x-row loads are in flight per chain.
__global__ void k_gather(const float* __restrict__ x,
                         float* __restrict__ out, int n) {
    int wrp  = blockIdx.x * (blockDim.x >> 5) + (threadIdx.x >> 5);
    int lane = threadIdx.x & 31;
    int q = lane >> 2;      // node slot within warp (0..7)
    int l = lane & 3;       // lane within node
    int i = wrp * 8 + q;
    if (i >= n) return;
    int r0 = g_rowptr[i];
    int r1 = g_rowptr[i + 1];
    float4 a0 = make_float4(0.f, 0.f, 0.f, 0.f);
    float4 a1 = make_float4(0.f, 0.f, 0.f, 0.f);
    float4 a2 = make_float4(0.f, 0.f, 0.f, 0.f);
    float4 a3 = make_float4(0.f, 0.f, 0.f, 0.f);
    int p = r0;
    for (; p + 1 < r1; p += 2) {
        int2 evA = g_edge[p];
        int2 evB = g_edge[p + 1];
        float vA = __int_as_float(evA.y);
        float vB = __int_as_float(evB.y);
        const float4* rowA = reinterpret_cast<const float4*>(x + (size_t)evA.x * 64);
        const float4* rowB = reinterpret_cast<const float4*>(x + (size_t)evB.x * 64);
        float4 xA0 = rowA[l];      float4 xB0 = rowB[l];
        float4 xA1 = rowA[l + 4];  float4 xB1 = rowB[l + 4];
        float4 xA2 = rowA[l + 8];  float4 xB2 = rowB[l + 8];
        float4 xA3 = rowA[l + 12]; float4 xB3 = rowB[l + 12];
        a0.x = fmaf(xA0.x, vA, a0.x); a0.y = fmaf(xA0.y, vA, a0.y);
        a0.z = fmaf(xA0.z, vA, a0.z); a0.w = fmaf(xA0.w, vA, a0.w);
        a1.x = fmaf(xA1.x, vA, a1.x); a1.y = fmaf(xA1.y, vA, a1.y);
        a1.z = fmaf(xA1.z, vA, a1.z); a1.w = fmaf(xA1.w, vA, a1.w);
        a2.x = fmaf(xA2.x, vA, a2.x); a2.y = fmaf(xA2.y, vA, a2.y);
        a2.z = fmaf(xA2.z, vA, a2.z); a2.w = fmaf(xA2.w, vA, a2.w);
        a3.x = fmaf(xA3.x, vA, a3.x); a3.y = fmaf(xA3.y, vA, a3.y);
        a3.z = fmaf(xA3.z, vA, a3.z); a3.w = fmaf(xA3.w, vA, a3.w);
        a0.x = fmaf(xB0.x, vB, a0.x); a0.y = fmaf(xB0.y, vB, a0.y);
        a0.z = fmaf(xB0.z, vB, a0.z); a0.w = fmaf(xB0.w, vB, a0.w);
        a1.x = fmaf(xB1.x, vB, a1.x); a1.y = fmaf(xB1.y, vB, a1.y);
        a1.z = fmaf(xB1.z, vB, a1.z); a1.w = fmaf(xB1.w, vB, a1.w);
        a2.x = fmaf(xB2.x, vB, a2.x); a2.y = fmaf(xB2.y, vB, a2.y);
        a2.z = fmaf(xB2.z, vB, a2.z); a2.w = fmaf(xB2.w, vB, a2.w);
        a3.x = fmaf(xB3.x, vB, a3.x); a3.y = fmaf(xB3.y, vB, a3.y);
        a3.z = fmaf(xB3.z, vB, a3.z); a3.w = fmaf(xB3.w, vB, a3.w);
    }
    if (p < r1) {
        int2 ev = g_edge[p];
        float v = __int_as_float(ev.y);
        const float4* row = reinterpret_cast<const float4*>(x + (size_t)ev.x * 64);
        float4 x0 = row[l];
        float4 x1 = row[l + 4];
        float4 x2 = row[l + 8];
        float4 x3 = row[l + 12];
        a0.x = fmaf(x0.x, v, a0.x); a0.y = fmaf(x0.y, v, a0.y);
        a0.z = fmaf(x0.z, v, a0.z); a0.w = fmaf(x0.w, v, a0.w);
        a1.x = fmaf(x1.x, v, a1.x); a1.y = fmaf(x1.y, v, a1.y);
        a1.z = fmaf(x1.z, v, a1.z); a1.w = fmaf(x1.w, v, a1.w);
        a2.x = fmaf(x2.x, v, a2.x); a2.y = fmaf(x2.y, v, a2.y);
        a2.z = fmaf(x2.z, v, a2.z); a2.w = fmaf(x2.w, v, a2.w);
        a3.x = fmaf(x3.x, v, a3.x); a3.y = fmaf(x3.y, v, a3.y);
        a3.z = fmaf(x3.z, v, a3.z); a3.w = fmaf(x3.w, v, a3.w);
    }
    a0.x = fmaxf(a0.x, 0.f); a0.y = fmaxf(a0.y, 0.f);
    a0.z = fmaxf(a0.z, 0.f); a0.w = fmaxf(a0.w, 0.f);
    a1.x = fmaxf(a1.x, 0.f); a1.y = fmaxf(a1.y, 0.f);
    a1.z = fmaxf(a1.z, 0.f); a1.w = fmaxf(a1.w, 0.f);
    a2.x = fmaxf(a2.x, 0.f); a2.y = fmaxf(a2.y, 0.f);
    a2.z = fmaxf(a2.z, 0.f); a2.w = fmaxf(a2.w, 0.f);
    a3.x = fmaxf(a3.x, 0.f); a3.y = fmaxf(a3.y, 0.f);
    a3.z = fmaxf(a3.z, 0.f); a3.w = fmaxf(a3.w, 0.f);
    float4* orow = reinterpret_cast<float4*>(out + (size_t)i * 64);
    orow[l]      = a0;
    orow[l + 4]  = a1;
    orow[l + 8]  = a2;
    orow[l + 12] = a3;
}

extern "C" void kernel_launch(void* const* d_in, const int* in_sizes, int n_in,
                              void* d_out, int out_size) {
    const float* x     = (const float*)d_in[0];
    const float* lin_w = (const float*)d_in[1];
    const float* lin_b = (const float*)d_in[2];
    const float* w1    = (const float*)d_in[3];
    const float* w2    = (const float*)d_in[4];
    const float* w3    = (const float*)d_in[5];
    const void*  ei    = d_in[6];
    float* out = (float*)d_out;

    int n = in_sizes[6] / 2;     // edge_index is (2, N)
    int first = n / 3;

    int dotBlocks    = (n + 15) / 16;       // 8 warps/block, 2 nodes/warp
    int gatherBlocks = (n + 63) / 64;       // 8 warps/block, 8 nodes/warp
    int edgeBlocks   = (n + 255) / 256;
    int scoreBlocks  = (n + 511) / 512;     // 2 edges/thread

    k_dot_init     <<<dotBlocks, 256>>>(x, lin_w, lin_b, ei, n);
    k_edge_scatter1<<<edgeBlocks, 256>>>(ei, lin_b, n, first);
    k_scan         <<<SCAN_NB, 256>>>(n);
    k_score_scatter<<<scoreBlocks, 256>>>(w1, w2, w3, n, first);
    k_gather       <<<gatherBlocks, 256>>>(x, out, n);
}